// round 10
// baseline (speedup 1.0000x reference)
#include <cuda_runtime.h>
#include <cstdint>

// SecConv2d on GB300 — final data model (validated by R1-R9 evidence):
//   device buffers: INT32 (x 32x64x56x56, w 64x64x3x3, b 64), values < 2^16
//   expected output: conv computed with int32 WRAPAROUND (mod 2^32),
//                    read back as FLOAT32.
// => compute sum mod 2^32 in pure u32 IMADs (exact = low 32 bits),
//    store (float)(int32)(sum + bias).

#define NTHREADS 224        // 2 kgroups x (8 rows x 14 colgroups)
#define TK 8                // k-channels per thread
#define TP 4                // pixels per thread
#define KT 16               // k-channels per CTA (2 kgroups x TK)
#define WSH_ELEMS (576*KT)  // 9216 u32 = 36KB static smem

__global__ void __launch_bounds__(NTHREADS)
secconv2d_u32(const int* __restrict__ x,
              const int* __restrict__ w,
              const int* __restrict__ bias,
              float* __restrict__ out)
{
    __shared__ unsigned int wsh[WSH_ELEMS];   // [r=0..575][kk=0..15]

    const int tid = threadIdx.x;
    const int kt  = blockIdx.x;     // 0..3  -> 16 output channels
    const int rt  = blockIdx.y;     // 0..6  -> 8 output rows (zero waste)
    const int n   = blockIdx.z;     // 0..31

    // Stage weights for this 16-channel tile: w flat = k*576 + r.
    for (int e = tid; e < WSH_ELEMS; e += NTHREADS) {
        int kk = e / 576;
        int r  = e - kk * 576;
        wsh[r * KT + kk] = (unsigned int)__ldg(&w[(kt * KT + kk) * 576 + r]);
    }
    __syncthreads();

    const int kg      = tid / 112;            // 0..1
    const int lane    = tid - kg * 112;       // 0..111
    const int row     = lane / 14;            // 0..7
    const int col4    = (lane - row * 14) * TP; // 0,4,...,52
    const int orow    = rt * 8 + row;         // 0..55, always valid
    const int kbase   = kt * KT + kg * TK;

    const int* xn = x + n * 200704;

    unsigned int acc[TK][TP];
    #pragma unroll
    for (int a = 0; a < TK; ++a)
        #pragma unroll
        for (int b = 0; b < TP; ++b) acc[a][b] = 0u;

    #pragma unroll 2
    for (int c = 0; c < 64; ++c) {
        const int* xc = xn + c * 3136;
        #pragma unroll
        for (int kh = 0; kh < 3; ++kh) {
            const int ir = orow - 1 + kh;
            // 6 input taps cover kw=0..2 for TP=4 consecutive pixels
            unsigned int xr[6];
            #pragma unroll
            for (int t = 0; t < 6; ++t) {
                const int ic = col4 - 1 + t;
                const bool ok = ((unsigned)ir < 56u) && ((unsigned)ic < 56u);
                xr[t] = ok ? (unsigned int)__ldg(xc + ir * 56 + ic) : 0u;
            }
            #pragma unroll
            for (int kw = 0; kw < 3; ++kw) {
                const int q = c * 9 + kh * 3 + kw;
                // 8 consecutive u32, 32B-aligned -> 2x LDS.128 (broadcast)
                const uint4* wr = (const uint4*)&wsh[q * KT + kg * TK];
                const uint4 w0 = wr[0];
                const uint4 w1 = wr[1];
                const unsigned int wv[TK] = {w0.x, w0.y, w0.z, w0.w,
                                             w1.x, w1.y, w1.z, w1.w};
                #pragma unroll
                for (int a = 0; a < TK; ++a)
                    #pragma unroll
                    for (int b = 0; b < TP; ++b)
                        acc[a][b] += xr[kw + b] * wv[a];   // u32 IMAD, mod 2^32
            }
        }
    }

    float* outn = out + n * 200704;
    #pragma unroll
    for (int a = 0; a < TK; ++a) {
        const int k = kbase + a;
        const unsigned int bv = (unsigned int)__ldg(&bias[k]);
        #pragma unroll
        for (int b = 0; b < TP; ++b) {
            // signed int32 interpretation of the wrapped sum, then f32
            int v = (int)(acc[a][b] + bv);
            outn[k * 3136 + orow * 56 + col4 + b] = (float)v;
        }
    }
}

extern "C" void kernel_launch(void* const* d_in, const int* in_sizes, int n_in,
                              void* d_out, int out_size)
{
    // Bind by size ranking: largest = x, smallest = bias, remaining = weight.
    int ix = 0, ib = 0;
    for (int i = 1; i < n_in; ++i) {
        if (in_sizes[i] > in_sizes[ix]) ix = i;
        if (in_sizes[i] < in_sizes[ib]) ib = i;
    }
    int iw = 0;
    for (int i = 0; i < n_in; ++i)
        if (i != ix && i != ib) { iw = i; break; }

    const int* x = (const int*)d_in[ix];
    const int* w = (const int*)d_in[iw];
    const int* b = (const int*)d_in[ib];
    float* out   = (float*)d_out;

    dim3 grid(4, 7, 32);   // 16k x 8rows x batch = 896 CTAs, zero waste
    secconv2d_u32<<<grid, NTHREADS>>>(x, w, b, out);
}